// round 3
// baseline (speedup 1.0000x reference)
#include <cuda_runtime.h>
#include <cuda_bf16.h>
#include <cstdint>

// Problem constants
#define B_  16
#define T_  512
#define E_  2048
#define H_  1024
#define D_  128
#define NCTA 32   // recurrence CTAs; CTA c owns h rows [32c, 32c+32)

// ---------------- device scratch (static globals: allowed) ----------------
__device__ float g_xw[(size_t)B_ * T_ * H_];   // 32 MB input projection
__device__ float g_hbuf[2][H_];                // double-buffered hidden state
__device__ float g_hs[B_ * H_];                // snapshot of h at end of each row
__device__ unsigned int g_flags[NCTA];         // per-CTA completed-step counters

// ---------------- acquire/release helpers ----------------
__device__ __forceinline__ unsigned int ld_acq(const unsigned int* p) {
    unsigned int v;
    asm volatile("ld.acquire.gpu.global.u32 %0, [%1];" : "=r"(v) : "l"(p) : "memory");
    return v;
}
__device__ __forceinline__ void st_rel(unsigned int* p, unsigned int v) {
    asm volatile("st.release.gpu.global.u32 [%0], %1;" :: "l"(p), "r"(v) : "memory");
}

// ---------------- init: reset flags + zero h (every graph replay) ----------------
__global__ void init_kernel() {
    int t = threadIdx.x;
    if (t < NCTA) g_flags[t] = 0;
    g_hbuf[0][t] = 0.0f;
    g_hbuf[1][t] = 0.0f;
}

// ---------------- kernel 1: xW = x @ W_ih^T + (b_ih + b_hh) ----------------
// A = x [8192, 2048] row-major, Bw = W_ih [1024, 2048] row-major (both K-major -> NT GEMM)
#define BM 128
#define BN 128
#define BK 16

__global__ void __launch_bounds__(256) gemm_xw_kernel(
    const float* __restrict__ A, const float* __restrict__ Bw,
    const float* __restrict__ bih, const float* __restrict__ bhh,
    const int* __restrict__ lengths, float* __restrict__ C)
{
    const int n0 = blockIdx.x * BN;
    const int m0 = blockIdx.y * BM;
    // Early exit: tile lies entirely within one batch row (512 % 128 == 0)
    const int b = m0 >> 9;
    if ((m0 & 511) >= lengths[b]) return;

    __shared__ float As[2][BK * BM];
    __shared__ float Bs[2][BK * BM];

    const int tid = threadIdx.x;
    const int tx = tid & 15;
    const int ty = tid >> 4;

    float4 ra[2], rb[2];

    // Each thread loads 2 float4 of A and B per K-tile.
    // slot s = tid*2+i: row = s>>2, kq = s&3 (float4 over k)
    auto ldg_tile = [&](int k0) {
#pragma unroll
        for (int i = 0; i < 2; i++) {
            int s = tid * 2 + i;
            int row = s >> 2;
            int kq = s & 3;
            ra[i] = *(const float4*)(A  + (size_t)(m0 + row) * E_ + k0 + kq * 4);
            rb[i] = *(const float4*)(Bw + (size_t)(n0 + row) * E_ + k0 + kq * 4);
        }
    };
    auto sts_tile = [&](int buf) {
#pragma unroll
        for (int i = 0; i < 2; i++) {
            int s = tid * 2 + i;
            int row = s >> 2;
            int kq = s & 3;
            As[buf][(kq * 4 + 0) * BM + row] = ra[i].x;
            As[buf][(kq * 4 + 1) * BM + row] = ra[i].y;
            As[buf][(kq * 4 + 2) * BM + row] = ra[i].z;
            As[buf][(kq * 4 + 3) * BM + row] = ra[i].w;
            Bs[buf][(kq * 4 + 0) * BM + row] = rb[i].x;
            Bs[buf][(kq * 4 + 1) * BM + row] = rb[i].y;
            Bs[buf][(kq * 4 + 2) * BM + row] = rb[i].z;
            Bs[buf][(kq * 4 + 3) * BM + row] = rb[i].w;
        }
    };

    ldg_tile(0);
    sts_tile(0);
    __syncthreads();

    float acc[8][8];
#pragma unroll
    for (int i = 0; i < 8; i++)
#pragma unroll
        for (int j = 0; j < 8; j++) acc[i][j] = 0.0f;

    const int NK = E_ / BK;  // 128
    for (int kt = 0; kt < NK; ++kt) {
        const int buf = kt & 1;
        if (kt + 1 < NK) ldg_tile((kt + 1) * BK);
#pragma unroll
        for (int kk = 0; kk < BK; ++kk) {
            float a[8], bb[8];
            *(float4*)(a)      = *(const float4*)&As[buf][kk * BM + ty * 8];
            *(float4*)(a + 4)  = *(const float4*)&As[buf][kk * BM + ty * 8 + 4];
            *(float4*)(bb)     = *(const float4*)&Bs[buf][kk * BM + tx * 8];
            *(float4*)(bb + 4) = *(const float4*)&Bs[buf][kk * BM + tx * 8 + 4];
#pragma unroll
            for (int i = 0; i < 8; i++)
#pragma unroll
                for (int j = 0; j < 8; j++)
                    acc[i][j] = fmaf(a[i], bb[j], acc[i][j]);
        }
        if (kt + 1 < NK) {
            sts_tile(buf ^ 1);
            __syncthreads();
        }
    }

    // epilogue: add (b_ih + b_hh)[n]
#pragma unroll
    for (int j = 0; j < 8; j++) {
        int n = n0 + tx * 8 + j;
        float bsum = bih[n] + bhh[n];
#pragma unroll
        for (int i = 0; i < 8; i++) {
            int m = m0 + ty * 8 + i;
            C[(size_t)m * H_ + n] = acc[i][j] + bsum;
        }
    }
}

// ---------------- kernel 2: persistent sequential recurrence ----------------
// 32 CTAs x 1024 threads. CTA c holds W_hh rows [32c,32c+32) in registers:
// lane l of warp w holds Wt[j] = W_hh[32c + l][32w + j]  (warp w owns k-chunk [32w,32w+32))
__global__ void __launch_bounds__(1024, 1) rnn_kernel(
    const float* __restrict__ xw, const int* __restrict__ lengths,
    const float* __restrict__ W_hh)
{
    const int c   = blockIdx.x;
    const int tid = threadIdx.x;
    const int w   = tid >> 5;
    const int l   = tid & 31;

    // Load W slice into registers (startup only)
    float Wt[32];
    {
        const float* wp = W_hh + (size_t)(32 * c + l) * H_ + 32 * w;
#pragma unroll
        for (int j = 0; j < 32; j += 4) {
            float4 v = *(const float4*)(wp + j);
            Wt[j] = v.x; Wt[j + 1] = v.y; Wt[j + 2] = v.z; Wt[j + 3] = v.w;
        }
    }

    __shared__ float sacc[32 * 33];
    __shared__ int slen[B_];
    if (tid < B_) slen[tid] = lengths[tid];
    __syncthreads();

    unsigned int step = 0;
    for (int b = 0; b < B_; ++b) {
        const int len = slen[b];
        for (int t = 0; t < len; ++t) {
            // prefetch xw for this step (independent of h) — in flight during spin
            float xwv = 0.0f;
            if (l == 0)
                xwv = __ldg(xw + ((size_t)(b * T_ + t)) * H_ + 32 * c + w);

            if (step > 0) {
                if (w == 0) {
                    unsigned int v;
                    do {
                        v = ld_acq(&g_flags[l]);   // NCTA == 32 == warp size
                    } while (__any_sync(0xffffffffu, v < step));
                }
                __syncthreads();
            }

            const int cur = step & 1;
            const int nxt = cur ^ 1;

            // lane l loads h[32w + l]  (== h[tid], fully coalesced 4KB)
            float hl = g_hbuf[cur][tid];

            // lane l accumulates row (32c+l)'s partial over chunk [32w,32w+32)
            float a0 = 0.f, a1 = 0.f, a2 = 0.f, a3 = 0.f;
#pragma unroll
            for (int j = 0; j < 32; j += 4) {
                float h0 = __shfl_sync(0xffffffffu, hl, j);
                float h1 = __shfl_sync(0xffffffffu, hl, j + 1);
                float h2 = __shfl_sync(0xffffffffu, hl, j + 2);
                float h3 = __shfl_sync(0xffffffffu, hl, j + 3);
                a0 = fmaf(Wt[j],     h0, a0);
                a1 = fmaf(Wt[j + 1], h1, a1);
                a2 = fmaf(Wt[j + 2], h2, a2);
                a3 = fmaf(Wt[j + 3], h3, a3);
            }
            float acc = (a0 + a1) + (a2 + a3);

            // sacc[row_local][chunk], pad 33 -> conflict-free both phases
            sacc[l * 33 + w] = acc;
            __syncthreads();

            // warp w reduces row w across 32 chunks
            float p = sacc[w * 33 + l];
#pragma unroll
            for (int o = 16; o > 0; o >>= 1)
                p += __shfl_xor_sync(0xffffffffu, p, o);

            if (l == 0) {
                float hn = tanhf(p + xwv);
                g_hbuf[nxt][32 * c + w] = hn;
                if (t == len - 1) g_hs[b * H_ + 32 * c + w] = hn;
            }
            __syncthreads();
            if (tid == 0) st_rel(&g_flags[c], step + 1);
            ++step;
        }
    }
}

// ---------------- kernel 3: out = hs @ W_l1^T + b_l1 ----------------
__global__ void proj_kernel(const float* __restrict__ Wl1,
                            const float* __restrict__ bl1,
                            float* __restrict__ out)
{
    const int b = blockIdx.x;
    const int w = threadIdx.x >> 5;
    const int l = threadIdx.x & 31;
    const int d = blockIdx.y * 4 + w;

    const float* h  = g_hs + b * H_;
    const float* wr = Wl1 + (size_t)d * H_;
    float s = 0.0f;
#pragma unroll
    for (int i = 0; i < 32; i++)
        s = fmaf(h[l + 32 * i], wr[l + 32 * i], s);
#pragma unroll
    for (int o = 16; o > 0; o >>= 1)
        s += __shfl_xor_sync(0xffffffffu, s, o);
    if (l == 0) out[b * D_ + d] = s + bl1[d];
}

// ---------------- launch ----------------
extern "C" void kernel_launch(void* const* d_in, const int* in_sizes, int n_in,
                              void* d_out, int out_size)
{
    const float* x       = (const float*)d_in[0];
    const int*   lengths = (const int*)d_in[1];
    const float* W_ih    = (const float*)d_in[2];
    const float* W_hh    = (const float*)d_in[3];
    const float* b_ih    = (const float*)d_in[4];
    const float* b_hh    = (const float*)d_in[5];
    const float* W_l1    = (const float*)d_in[6];
    const float* b_l1    = (const float*)d_in[7];
    float* out = (float*)d_out;

    float* xw_ptr;
    cudaGetSymbolAddress((void**)&xw_ptr, g_xw);

    init_kernel<<<1, 1024>>>();

    dim3 ggrid(H_ / BN, (B_ * T_) / BM);  // (8, 64)
    gemm_xw_kernel<<<ggrid, 256>>>(x, W_ih, b_ih, b_hh, lengths, xw_ptr);

    rnn_kernel<<<NCTA, 1024>>>(xw_ptr, lengths, W_hh);

    dim3 pgrid(B_, D_ / 4);  // (16, 32)
    proj_kernel<<<pgrid, 128>>>(W_l1, b_l1, out);
}

// round 9
// speedup vs baseline: 1.6763x; 1.6763x over previous
#include <cuda_runtime.h>
#include <cuda_bf16.h>
#include <cstdint>

// Problem constants
#define B_  16
#define T_  512
#define E_  2048
#define H_  1024
#define D_  128
#define NCTA 32   // recurrence CTAs; CTA c owns h rows [32c, 32c+32)

// ---------------- device scratch (static globals: allowed) ----------------
__device__ float g_xw[(size_t)B_ * T_ * H_];   // 32 MB input projection
// Parity-double-buffered tagged hidden state: buffer (s&1) holds the input of
// step s. Each element is ONE aligned u64 {lo: h bits, hi: tag}. Accessed only
// with relaxed.gpu 64-bit atomics: morally strong (guaranteed visibility /
// spin progress), single-copy atomic (tag+data can never tear), and free of
// fence cost. The 2-deep ring covers the provable <=1-step inter-CTA skew.
__device__ unsigned long long g_htag[2][H_];
__device__ float g_hs[B_ * H_];                // snapshot of h at end of each row

// ---------------- relaxed 64-bit tagged-word helpers ----------------
__device__ __forceinline__ unsigned long long ld_rlx_u64(const unsigned long long* p) {
    unsigned long long v;
    asm volatile("ld.relaxed.gpu.global.u64 %0, [%1];" : "=l"(v) : "l"(p) : "memory");
    return v;
}
__device__ __forceinline__ void st_rlx_u64(unsigned long long* p, unsigned long long v) {
    asm volatile("st.relaxed.gpu.global.u64 [%0], %1;" :: "l"(p), "l"(v) : "memory");
}

// ---------------- init: reset tags + zero h (every graph replay) ----------------
__global__ void init_kernel() {
    int t = threadIdx.x;
    g_htag[0][t] = 0ull;  // h = 0.0f, tag = 0 (input for step 0)
    g_htag[1][t] = 0ull;  // tag 0 < 1: never valid for odd steps until published
}

// ---------------- kernel 1: xW = x @ W_ih^T + (b_ih + b_hh) ----------------
// A = x [8192, 2048] row-major, Bw = W_ih [1024, 2048] row-major (NT GEMM)
#define BM 128
#define BN 128
#define BK 16

__global__ void __launch_bounds__(256) gemm_xw_kernel(
    const float* __restrict__ A, const float* __restrict__ Bw,
    const float* __restrict__ bih, const float* __restrict__ bhh,
    const int* __restrict__ lengths, float* __restrict__ C)
{
    const int n0 = blockIdx.x * BN;
    const int m0 = blockIdx.y * BM;
    // Early exit: tile lies entirely within one batch row (512 % 128 == 0)
    const int b = m0 >> 9;
    if ((m0 & 511) >= lengths[b]) return;

    __shared__ float As[2][BK * BM];
    __shared__ float Bs[2][BK * BM];

    const int tid = threadIdx.x;
    const int tx = tid & 15;
    const int ty = tid >> 4;

    float4 ra[2], rb[2];

    auto ldg_tile = [&](int k0) {
#pragma unroll
        for (int i = 0; i < 2; i++) {
            int s = tid * 2 + i;
            int row = s >> 2;
            int kq = s & 3;
            ra[i] = *(const float4*)(A  + (size_t)(m0 + row) * E_ + k0 + kq * 4);
            rb[i] = *(const float4*)(Bw + (size_t)(n0 + row) * E_ + k0 + kq * 4);
        }
    };
    auto sts_tile = [&](int buf) {
#pragma unroll
        for (int i = 0; i < 2; i++) {
            int s = tid * 2 + i;
            int row = s >> 2;
            int kq = s & 3;
            As[buf][(kq * 4 + 0) * BM + row] = ra[i].x;
            As[buf][(kq * 4 + 1) * BM + row] = ra[i].y;
            As[buf][(kq * 4 + 2) * BM + row] = ra[i].z;
            As[buf][(kq * 4 + 3) * BM + row] = ra[i].w;
            Bs[buf][(kq * 4 + 0) * BM + row] = rb[i].x;
            Bs[buf][(kq * 4 + 1) * BM + row] = rb[i].y;
            Bs[buf][(kq * 4 + 2) * BM + row] = rb[i].z;
            Bs[buf][(kq * 4 + 3) * BM + row] = rb[i].w;
        }
    };

    ldg_tile(0);
    sts_tile(0);
    __syncthreads();

    float acc[8][8];
#pragma unroll
    for (int i = 0; i < 8; i++)
#pragma unroll
        for (int j = 0; j < 8; j++) acc[i][j] = 0.0f;

    const int NK = E_ / BK;  // 128
    for (int kt = 0; kt < NK; ++kt) {
        const int buf = kt & 1;
        if (kt + 1 < NK) ldg_tile((kt + 1) * BK);
#pragma unroll
        for (int kk = 0; kk < BK; ++kk) {
            float a[8], bb[8];
            *(float4*)(a)      = *(const float4*)&As[buf][kk * BM + ty * 8];
            *(float4*)(a + 4)  = *(const float4*)&As[buf][kk * BM + ty * 8 + 4];
            *(float4*)(bb)     = *(const float4*)&Bs[buf][kk * BM + tx * 8];
            *(float4*)(bb + 4) = *(const float4*)&Bs[buf][kk * BM + tx * 8 + 4];
#pragma unroll
            for (int i = 0; i < 8; i++)
#pragma unroll
                for (int j = 0; j < 8; j++)
                    acc[i][j] = fmaf(a[i], bb[j], acc[i][j]);
        }
        if (kt + 1 < NK) {
            sts_tile(buf ^ 1);
            __syncthreads();
        }
    }

#pragma unroll
    for (int j = 0; j < 8; j++) {
        int n = n0 + tx * 8 + j;
        float bsum = bih[n] + bhh[n];
#pragma unroll
        for (int i = 0; i < 8; i++) {
            int m = m0 + ty * 8 + i;
            C[(size_t)m * H_ + n] = acc[i][j] + bsum;
        }
    }
}

// ---------------- kernel 2: persistent sequential recurrence ----------------
// 32 CTAs x 1024 threads. CTA c holds W_hh rows [32c,32c+32) in registers:
// lane l of warp w holds Wt[j] = W_hh[32c + l][32w + j] (warp w owns k-chunk [32w,32w+32))
//
// Sync: tagged u64 words in a 2-deep parity ring. Consumer warp w spins
// (warp-converged, relaxed 64-bit atomic loads -> guaranteed progress) on its
// own words g_htag[s&1][tid] until tag >= s; the h value rides in the same
// single-copy-atomic word. Producer publishes step-s results into buffer
// (s+1)&1 with tag s+1. WAR safety: overwriting buffer s&1 with tag s+2
// requires completing step s+1, which requires every CTA to have published
// tag s+1, which requires every CTA to have consumed its step-s inputs.
__global__ void __launch_bounds__(1024, 1) rnn_kernel(
    const float* __restrict__ xw, const int* __restrict__ lengths,
    const float* __restrict__ W_hh)
{
    const int c   = blockIdx.x;
    const int tid = threadIdx.x;
    const int w   = tid >> 5;
    const int l   = tid & 31;

    // Load W slice into registers (startup only)
    float Wt[32];
    {
        const float* wp = W_hh + (size_t)(32 * c + l) * H_ + 32 * w;
#pragma unroll
        for (int j = 0; j < 32; j += 4) {
            float4 v = *(const float4*)(wp + j);
            Wt[j] = v.x; Wt[j + 1] = v.y; Wt[j + 2] = v.z; Wt[j + 3] = v.w;
        }
    }

    __shared__ float sacc[2][32 * 33];  // parity double-buffered partials
    __shared__ float hnew[32];          // per-step new h slice (rows 32c..32c+31)
    __shared__ int slen[B_];
    if (tid < B_) slen[tid] = lengths[tid];
    __syncthreads();

    unsigned int s = 0;  // global step counter (valid steps only)
    for (int b = 0; b < B_; ++b) {
        const int len = slen[b];
        for (int t = 0; t < len; ++t) {
            const int par = s & 1;

            // prefetch xw for this step (independent of h) — in flight during spin
            float xwv = 0.0f;
            if (l == 0)
                xwv = __ldg(xw + ((size_t)(b * T_ + t)) * H_ + 32 * c + w);

            // warp-converged spin on own tagged h words (tid indexes rows
            // [32w, 32w+32) — exactly the chunk this warp consumes)
            unsigned long long hv;
            do {
                hv = ld_rlx_u64(&g_htag[par][tid]);
            } while (__any_sync(0xffffffffu, (unsigned int)(hv >> 32) < s));
            const float hl = __uint_as_float((unsigned int)hv);

            // lane l accumulates row (32c+l)'s partial over chunk [32w,32w+32)
            float a0 = 0.f, a1 = 0.f, a2 = 0.f, a3 = 0.f;
#pragma unroll
            for (int j = 0; j < 32; j += 4) {
                float h0 = __shfl_sync(0xffffffffu, hl, j);
                float h1 = __shfl_sync(0xffffffffu, hl, j + 1);
                float h2 = __shfl_sync(0xffffffffu, hl, j + 2);
                float h3 = __shfl_sync(0xffffffffu, hl, j + 3);
                a0 = fmaf(Wt[j],     h0, a0);
                a1 = fmaf(Wt[j + 1], h1, a1);
                a2 = fmaf(Wt[j + 2], h2, a2);
                a3 = fmaf(Wt[j + 3], h3, a3);
            }
            sacc[par][l * 33 + w] = (a0 + a1) + (a2 + a3);
            __syncthreads();

            // warp w reduces row (32c+w) across 32 chunks
            float p = sacc[par][w * 33 + l];
#pragma unroll
            for (int o = 16; o > 0; o >>= 1)
                p += __shfl_xor_sync(0xffffffffu, p, o);

            if (l == 0)
                hnew[w] = tanhf(p + xwv);
            __syncthreads();

            // warp 0 publishes the whole 32-row slice into the OTHER parity
            // buffer: one coalesced 256B burst of relaxed u64 stores
            if (w == 0) {
                float hn = hnew[l];
                unsigned long long word =
                    ((unsigned long long)(s + 1) << 32) |
                    (unsigned long long)__float_as_uint(hn);
                st_rlx_u64(&g_htag[par ^ 1][32 * c + l], word);
                if (t == len - 1)
                    g_hs[b * H_ + 32 * c + l] = hn;
            }
            ++s;
        }
    }
}

// ---------------- kernel 3: out = hs @ W_l1^T + b_l1 ----------------
__global__ void proj_kernel(const float* __restrict__ Wl1,
                            const float* __restrict__ bl1,
                            float* __restrict__ out)
{
    const int b = blockIdx.x;
    const int w = threadIdx.x >> 5;
    const int l = threadIdx.x & 31;
    const int d = blockIdx.y * 4 + w;

    const float* h  = g_hs + b * H_;
    const float* wr = Wl1 + (size_t)d * H_;
    float s = 0.0f;
#pragma unroll
    for (int i = 0; i < 32; i++)
        s = fmaf(h[l + 32 * i], wr[l + 32 * i], s);
#pragma unroll
    for (int o = 16; o > 0; o >>= 1)
        s += __shfl_xor_sync(0xffffffffu, s, o);
    if (l == 0) out[b * D_ + d] = s + bl1[d];
}

// ---------------- launch ----------------
extern "C" void kernel_launch(void* const* d_in, const int* in_sizes, int n_in,
                              void* d_out, int out_size)
{
    const float* x       = (const float*)d_in[0];
    const int*   lengths = (const int*)d_in[1];
    const float* W_ih    = (const float*)d_in[2];
    const float* W_hh    = (const float*)d_in[3];
    const float* b_ih    = (const float*)d_in[4];
    const float* b_hh    = (const float*)d_in[5];
    const float* W_l1    = (const float*)d_in[6];
    const float* b_l1    = (const float*)d_in[7];
    float* out = (float*)d_out;

    float* xw_ptr;
    cudaGetSymbolAddress((void**)&xw_ptr, g_xw);

    init_kernel<<<1, 1024>>>();

    dim3 ggrid(H_ / BN, (B_ * T_) / BM);  // (8, 64)
    gemm_xw_kernel<<<ggrid, 256>>>(x, W_ih, b_ih, b_hh, lengths, xw_ptr);

    rnn_kernel<<<NCTA, 1024>>>(xw_ptr, lengths, W_hh);

    dim3 pgrid(B_, D_ / 4);  // (16, 32)
    proj_kernel<<<pgrid, 128>>>(W_l1, b_l1, out);
}